// round 13
// baseline (speedup 1.0000x reference)
#include <cuda_runtime.h>
#include <cuda_fp16.h>
#include <cstdint>
#include <cstddef>

// Flash attention, all-fp16 operand path, register-resident P, cp.async fp16
// tiles + cp.async mask staging (coalesced gmem, conflict-free LDS fragments),
// m16-per-warp / 4 CTAs per SM.
//   Prepass: K,V f32 (N,S,H,E) -> fp16 (N,H,S,E) __device__ scratch.
//   Main:    QK^T fp16 2-term split (m16n8k16); PV fp16 m16n8k16 f32-accum;
//            ldmatrix fragments; P in registers (C-frag == A-frag for k16).

#define N_DIM 2
#define L_DIM 2048
#define S_DIM 2048
#define H_DIM 16
#define BR 64
#define BC 32
#define NTILES (S_DIM / BC)
#define TEMP 0.125f

// smem byte layout
#define KROWB 144              // 64 fp16 = 128 B + 16 pad (ldmatrix conflict-free)
#define VROWB 144
#define MROWB 160              // 32 f32 = 128 B + 32 pad (LDS.64 frag conflict-free)
#define KBUFB 4608             // 32 * 144
#define VBUFB 4608
#define MBUFB 10240            // 64 * 160
#define OFF_KB 0               // 2 buffers -> 9216
#define OFF_VB 9216            // 2 buffers -> 9216 (end 18432)
#define OFF_MB 18432           // 2 buffers -> 20480 (end 38912)
#define QSTRIDE 68             // prologue scratch stride (floats); 64*68*4 = 17408
#define SMEM_BYTES 38912

// fp16 scratch, (N,H,S,E) layout
__device__ __align__(16) uint16_t g_KH[(size_t)N_DIM * H_DIM * S_DIM * 64];
__device__ __align__(16) uint16_t g_VH[(size_t)N_DIM * H_DIM * S_DIM * 64];

__device__ __forceinline__ uint32_t pack_f16(float lo, float hi) {
    uint32_t r; asm("cvt.rn.f16x2.f32 %0, %1, %2;" : "=r"(r) : "f"(hi), "f"(lo)); return r;
}
__device__ __forceinline__ float2 unpack_f16(uint32_t u) {
    __half2 h = *reinterpret_cast<__half2*>(&u);
    return __half22float2(h);
}

__device__ __forceinline__ void mma_f16(float* d, const uint32_t* a, uint32_t b0, uint32_t b1) {
    asm volatile(
        "mma.sync.aligned.m16n8k16.row.col.f32.f16.f16.f32 "
        "{%0,%1,%2,%3}, {%4,%5,%6,%7}, {%8,%9}, {%0,%1,%2,%3};"
        : "+f"(d[0]), "+f"(d[1]), "+f"(d[2]), "+f"(d[3])
        : "r"(a[0]), "r"(a[1]), "r"(a[2]), "r"(a[3]), "r"(b0), "r"(b1));
}

#define LDSM_X4(r0, r1, r2, r3, a) \
    asm volatile("ldmatrix.sync.aligned.m8n8.x4.shared.b16 {%0,%1,%2,%3}, [%4];" \
        : "=r"(r0), "=r"(r1), "=r"(r2), "=r"(r3) : "r"(a))
#define LDSM_X4_T(r0, r1, r2, r3, a) \
    asm volatile("ldmatrix.sync.aligned.m8n8.x4.trans.shared.b16 {%0,%1,%2,%3}, [%4];" \
        : "=r"(r0), "=r"(r1), "=r"(r2), "=r"(r3) : "r"(a))

#define CP_ASYNC16(dst, src) \
    asm volatile("cp.async.cg.shared.global [%0], [%1], 16;" :: "r"(dst), "l"(src))
#define CP_COMMIT() asm volatile("cp.async.commit_group;" ::: "memory")
#define CP_WAIT0()  asm volatile("cp.async.wait_group 0;" ::: "memory")

// ---- Prepass: f32 (N,S,H,E) -> fp16 (N,H,S,E) for K and V ----
#define GROUPS_PER_T ((N_DIM * S_DIM * H_DIM * 64) / 4)

__global__ __launch_bounds__(256) void cvt_kernel(
    const float* __restrict__ K, const float* __restrict__ V)
{
    int idx = blockIdx.x * blockDim.x + threadIdx.x;
    const bool isV = idx >= GROUPS_PER_T;
    int i = idx & (GROUPS_PER_T - 1);
    const float* src = isV ? V : K;
    uint16_t* dst = isV ? g_VH : g_KH;

    int e4 = i & 15;
    int h  = (i >> 4) & 15;
    int s  = (i >> 8) & 2047;
    int n  = i >> 19;

    float4 v = *(const float4*)(src + ((((size_t)n * S_DIM + s) * H_DIM + h) << 6) + e4 * 4);
    uint2 o = make_uint2(pack_f16(v.x, v.y), pack_f16(v.z, v.w));
    *(uint2*)(dst + ((((size_t)n * H_DIM + h) * S_DIM + s) << 6) + e4 * 4) = o;
}

__global__ __launch_bounds__(128, 4) void attn_mma11_kernel(
    const float* __restrict__ Q,
    const float* __restrict__ M,
    float* __restrict__ O)
{
    __shared__ __align__(128) char smb[SMEM_BYTES];
    float* smf = (float*)smb;
    const uint32_t smu = (uint32_t)__cvta_generic_to_shared(smb);

    const int tid  = threadIdx.x;
    const int w    = tid >> 5;
    const int lane = tid & 31;
    const int g    = lane >> 2;
    const int tg   = lane & 3;
    const int mm   = lane >> 3;
    const int rr   = lane & 7;

    const int qt = blockIdx.x % (L_DIM / BR);
    const int nh = blockIdx.x / (L_DIM / BR);
    const int h  = nh % H_DIM;
    const int n  = nh / H_DIM;
    const int qbase = qt * BR;

    const float* Qg = Q + (((size_t)n * L_DIM + qbase) * H_DIM + h) * 64;

    // ---- Prologue: Q (64x64) -> smem scratch -> fp16 hi/mid A frags ----
    #pragma unroll
    for (int i = 0; i < 8; i++) {
        int idx = i * 128 + tid;
        int row = idx >> 4, c4 = idx & 15;
        float4 v = *(const float4*)(Qg + (size_t)row * (H_DIM * 64) + c4 * 4);
        *(float4*)(smf + row * QSTRIDE + c4 * 4) = v;
    }
    __syncthreads();

    uint32_t qh[16], qm[16];
    {
        const int r0 = w * 16 + g;
        #pragma unroll
        for (int c = 0; c < 4; c++) {
            #pragma unroll
            for (int j = 0; j < 4; j++) {
                int row = r0 + ((j & 1) ? 8 : 0);
                int col = c * 16 + 2 * tg + ((j & 2) ? 8 : 0);
                float2 v = *(const float2*)(smf + row * QSTRIDE + col);
                float x0 = v.x * TEMP, x1 = v.y * TEMP;
                uint32_t hp = pack_f16(x0, x1);
                float2 hf = unpack_f16(hp);
                qh[c * 4 + j] = hp;
                qm[c * 4 + j] = pack_f16(x0 - hf.x, x1 - hf.y);
            }
        }
    }
    __syncthreads();   // scratch reads done before cp.async overwrites region

    float oacc[32];
    #pragma unroll
    for (int i = 0; i < 32; i++) oacc[i] = 0.0f;
    float rs0 = 0.0f, rs1 = 0.0f;

    const uint32_t kadr0 = smu + OFF_KB + (uint32_t)(((mm >> 1) * 8 + rr) * KROWB + (mm & 1) * 16);
    const uint32_t vadr0 = smu + OFF_VB + (uint32_t)(((mm & 1) * 8 + rr) * VROWB + (mm >> 1) * 16);

    // cp.async K/V mapping: rows tid>>3 and +16, 16B chunk (tid&7)
    const int crow = tid >> 3;
    const int ccol = tid & 7;
    const uint16_t* KHb = g_KH + (((size_t)n * H_DIM + h) * S_DIM << 6) + ccol * 8;
    const uint16_t* VHb = g_VH + (((size_t)n * H_DIM + h) * S_DIM << 6) + ccol * 8;
    const uint32_t kdst_t = smu + OFF_KB + crow * KROWB + ccol * 16;
    const uint32_t vdst_t = smu + OFF_VB + crow * VROWB + ccol * 16;

    // cp.async mask mapping: row tid>>1 (0..63), 4 chunks at (tid&1)*4 + j
    const int mrow = tid >> 1;
    const int mch0 = (tid & 1) * 4;
    const float* Mg = M + (size_t)(qbase + mrow) * S_DIM + mch0 * 4;
    const uint32_t mdst_t = smu + OFF_MB + mrow * MROWB + mch0 * 16;
    // mask fragment read base (floats): row (w*16+g), stride 40 words
    const float* mrd0 = (const float*)(smb + OFF_MB) + (w * 16 + g) * 40 + 2 * tg;

    // issue tile 0 (K, V, mask)
    {
        CP_ASYNC16(kdst_t,               KHb + (size_t)crow * 64);
        CP_ASYNC16(kdst_t + 16 * KROWB,  KHb + (size_t)(crow + 16) * 64);
        CP_ASYNC16(vdst_t,               VHb + (size_t)crow * 64);
        CP_ASYNC16(vdst_t + 16 * VROWB,  VHb + (size_t)(crow + 16) * 64);
        #pragma unroll
        for (int j = 0; j < 4; j++)
            CP_ASYNC16(mdst_t + j * 16, Mg + j * 4);
        CP_COMMIT();
    }

    for (int t = 0; t < NTILES; ++t) {
        const int buf = t & 1;
        const int s0 = t * BC;

        CP_WAIT0();        // tile t data arrived
        __syncthreads();   // visible; everyone done reading buf^1 (tile t-1)

        // issue tile t+1 into the other buffer (hidden behind compute below)
        if (t + 1 < NTILES) {
            const uint32_t ko = (uint32_t)((1 - buf) * KBUFB);
            const uint32_t vo = (uint32_t)((1 - buf) * VBUFB);
            const uint32_t mo = (uint32_t)((1 - buf) * MBUFB);
            const uint16_t* ks = KHb + (size_t)(s0 + BC) * 64;
            const uint16_t* vs = VHb + (size_t)(s0 + BC) * 64;
            CP_ASYNC16(kdst_t + ko,              ks + (size_t)crow * 64);
            CP_ASYNC16(kdst_t + ko + 16 * KROWB, ks + (size_t)(crow + 16) * 64);
            CP_ASYNC16(vdst_t + vo,              vs + (size_t)crow * 64);
            CP_ASYNC16(vdst_t + vo + 16 * VROWB, vs + (size_t)(crow + 16) * 64);
            #pragma unroll
            for (int j = 0; j < 4; j++)
                CP_ASYNC16(mdst_t + mo + j * 16, Mg + (s0 + BC) + j * 4);
            CP_COMMIT();
        }

        // ---- MMA1: S = (qh + qm) * kh, B frags via ldmatrix ----
        const uint32_t kadr = kadr0 + buf * KBUFB;
        float sf[16];
        #pragma unroll
        for (int i = 0; i < 16; i++) sf[i] = 0.0f;
        #pragma unroll
        for (int c = 0; c < 4; c++) {
            uint32_t b00, b01, b10, b11, b20, b21, b30, b31;
            LDSM_X4(b00, b01, b10, b11, kadr + c * 32);          // nt 0,1
            LDSM_X4(b20, b21, b30, b31, kadr + c * 32 + 2304);   // nt 2,3
            mma_f16(sf + 0,  qh + c * 4, b00, b01);
            mma_f16(sf + 0,  qm + c * 4, b00, b01);
            mma_f16(sf + 4,  qh + c * 4, b10, b11);
            mma_f16(sf + 4,  qm + c * 4, b10, b11);
            mma_f16(sf + 8,  qh + c * 4, b20, b21);
            mma_f16(sf + 8,  qm + c * 4, b20, b21);
            mma_f16(sf + 12, qh + c * 4, b30, b31);
            mma_f16(sf + 12, qm + c * 4, b30, b31);
        }

        // ---- softmax -> P fp16x2 A-fragments in registers (mask from smem) ----
        const float* mrd = mrd0 + buf * (MBUFB / 4);
        uint32_t u[8];
        #pragma unroll
        for (int nt = 0; nt < 4; nt++) {
            float2 a = *(const float2*)(mrd + nt * 8);
            float2 b = *(const float2*)(mrd + 8 * 40 + nt * 8);
            float p0 = __expf(sf[nt * 4 + 0] + TEMP * a.x);
            float p1 = __expf(sf[nt * 4 + 1] + TEMP * a.y);
            float p2 = __expf(sf[nt * 4 + 2] + TEMP * b.x);
            float p3 = __expf(sf[nt * 4 + 3] + TEMP * b.y);
            uint32_t u01 = pack_f16(p0, p1);
            uint32_t u23 = pack_f16(p2, p3);
            float2 t01 = unpack_f16(u01);
            float2 t23 = unpack_f16(u23);
            rs0 += t01.x + t01.y;
            rs1 += t23.x + t23.y;
            u[nt * 2 + 0] = u01;
            u[nt * 2 + 1] = u23;
        }

        // ---- MMA2: O += P * V; A from registers, B via ldmatrix.trans ----
        const uint32_t vadr = vadr0 + buf * VBUFB;
        #pragma unroll
        for (int kc = 0; kc < 2; kc++) {
            const uint32_t* a0 = u + 4 * kc;
            #pragma unroll
            for (int nvp = 0; nvp < 8; nvp += 2) {
                uint32_t v0, v1, v2, v3;
                LDSM_X4_T(v0, v1, v2, v3, vadr + kc * 2304 + nvp * 16);
                mma_f16(oacc + nvp * 4,     a0, v0, v1);
                mma_f16(oacc + nvp * 4 + 4, a0, v2, v3);
            }
        }
    }

    // ---- epilogue ----
    rs0 += __shfl_xor_sync(0xFFFFFFFFu, rs0, 1);
    rs0 += __shfl_xor_sync(0xFFFFFFFFu, rs0, 2);
    rs1 += __shfl_xor_sync(0xFFFFFFFFu, rs1, 1);
    rs1 += __shfl_xor_sync(0xFFFFFFFFu, rs1, 2);
    const float inv0 = 1.0f / rs0;
    const float inv1 = 1.0f / rs1;

    const int qrow0 = qbase + w * 16 + g;
    float* Og0 = O + (((size_t)n * L_DIM + qrow0) * H_DIM + h) * 64;
    float* Og1 = Og0 + (size_t)8 * H_DIM * 64;
    #pragma unroll
    for (int nt = 0; nt < 8; nt++) {
        int c = nt * 8 + tg * 2;
        float2 v0, v1;
        v0.x = oacc[nt * 4 + 0] * inv0;
        v0.y = oacc[nt * 4 + 1] * inv0;
        v1.x = oacc[nt * 4 + 2] * inv1;
        v1.y = oacc[nt * 4 + 3] * inv1;
        *(float2*)(Og0 + c) = v0;
        *(float2*)(Og1 + c) = v1;
    }
}

extern "C" void kernel_launch(void* const* d_in, const int* in_sizes, int n_in,
                              void* d_out, int out_size)
{
    (void)in_sizes; (void)n_in; (void)out_size;
    const float* q = (const float*)d_in[0];
    const float* k = (const float*)d_in[1];
    const float* v = (const float*)d_in[2];
    const float* m = (const float*)d_in[3];
    float* o = (float*)d_out;

    cvt_kernel<<<(2 * GROUPS_PER_T) / 256, 256>>>(k, v);

    dim3 grid(N_DIM * H_DIM * (L_DIM / BR));   // 1024
    dim3 block(128);
    attn_mma11_kernel<<<grid, block>>>(q, m, o);
}

// round 14
// speedup vs baseline: 1.2626x; 1.2626x over previous
#include <cuda_runtime.h>
#include <cuda_fp16.h>
#include <cstdint>
#include <cstddef>

// Flash attention, all-fp16 operand path, register-resident P, cp.async fp16
// K/V/mask tiles, mask folded into MMA1 C-initialization via ldmatrix
// (C-frag layout == ldmatrix.x4 layout for row-major 16x32 fp16 tile).
//   Prepass: K,V f32 -> fp16 (N,H,S,E); mask f32 -> fp16 TEMP*M (L,S).
//   Main:    QK^T fp16 2-term split (m16n8k16), C initialized with mask;
//            PV fp16 m16n8k16 f32-accum; P in registers.
//   m16-per-warp, 4 CTAs/SM.

#define N_DIM 2
#define L_DIM 2048
#define S_DIM 2048
#define H_DIM 16
#define BR 64
#define BC 32
#define NTILES (S_DIM / BC)
#define TEMP 0.125f

// smem byte layout
#define KROWB 144              // 64 fp16 = 128 B + 16 pad
#define VROWB 144
#define MROWB 80               // 32 fp16 = 64 B + 16 pad (ldmatrix conflict-free)
#define KBUFB 4608             // 32 * 144
#define VBUFB 4608
#define MBUFB 5120             // 64 * 80
#define OFF_KB 0               // 2 buffers -> 9216
#define OFF_VB 9216            // 2 buffers -> 9216 (end 18432)
#define OFF_MB 18432           // 2 buffers -> 10240 (end 28672)
#define QSTRIDE 68             // prologue scratch stride (floats); 64*68*4 = 17408
#define SMEM_BYTES 28672

// fp16 scratch
__device__ __align__(16) uint16_t g_KH[(size_t)N_DIM * H_DIM * S_DIM * 64];
__device__ __align__(16) uint16_t g_VH[(size_t)N_DIM * H_DIM * S_DIM * 64];
__device__ __align__(16) uint16_t g_MH[(size_t)L_DIM * S_DIM];   // TEMP*M, (L,S)

__device__ __forceinline__ uint32_t pack_f16(float lo, float hi) {
    uint32_t r; asm("cvt.rn.f16x2.f32 %0, %1, %2;" : "=r"(r) : "f"(hi), "f"(lo)); return r;
}
__device__ __forceinline__ float2 unpack_f16(uint32_t u) {
    __half2 h = *reinterpret_cast<__half2*>(&u);
    return __half22float2(h);
}

__device__ __forceinline__ void mma_f16(float* d, const uint32_t* a, uint32_t b0, uint32_t b1) {
    asm volatile(
        "mma.sync.aligned.m16n8k16.row.col.f32.f16.f16.f32 "
        "{%0,%1,%2,%3}, {%4,%5,%6,%7}, {%8,%9}, {%0,%1,%2,%3};"
        : "+f"(d[0]), "+f"(d[1]), "+f"(d[2]), "+f"(d[3])
        : "r"(a[0]), "r"(a[1]), "r"(a[2]), "r"(a[3]), "r"(b0), "r"(b1));
}

#define LDSM_X4(r0, r1, r2, r3, a) \
    asm volatile("ldmatrix.sync.aligned.m8n8.x4.shared.b16 {%0,%1,%2,%3}, [%4];" \
        : "=r"(r0), "=r"(r1), "=r"(r2), "=r"(r3) : "r"(a))
#define LDSM_X4_T(r0, r1, r2, r3, a) \
    asm volatile("ldmatrix.sync.aligned.m8n8.x4.trans.shared.b16 {%0,%1,%2,%3}, [%4];" \
        : "=r"(r0), "=r"(r1), "=r"(r2), "=r"(r3) : "r"(a))

#define CP_ASYNC16(dst, src) \
    asm volatile("cp.async.cg.shared.global [%0], [%1], 16;" :: "r"(dst), "l"(src))
#define CP_COMMIT() asm volatile("cp.async.commit_group;" ::: "memory")
#define CP_WAIT0()  asm volatile("cp.async.wait_group 0;" ::: "memory")

// ---- Prepass: K,V f32 -> fp16 (N,H,S,E); mask -> fp16 TEMP*M (L,S) ----
#define GROUPS_PER_T ((N_DIM * S_DIM * H_DIM * 64) / 4)     // 1048576
#define MGROUPS ((L_DIM * S_DIM) / 4)                        // 1048576

__global__ __launch_bounds__(256) void cvt_kernel(
    const float* __restrict__ K, const float* __restrict__ V,
    const float* __restrict__ M)
{
    int idx = blockIdx.x * blockDim.x + threadIdx.x;
    if (idx >= 2 * GROUPS_PER_T) {                 // mask part
        int i = idx - 2 * GROUPS_PER_T;
        float4 v = *(const float4*)(M + (size_t)i * 4);
        uint2 o = make_uint2(pack_f16(v.x * TEMP, v.y * TEMP),
                             pack_f16(v.z * TEMP, v.w * TEMP));
        *(uint2*)(g_MH + (size_t)i * 4) = o;
        return;
    }
    const bool isV = idx >= GROUPS_PER_T;
    int i = idx & (GROUPS_PER_T - 1);
    const float* src = isV ? V : K;
    uint16_t* dst = isV ? g_VH : g_KH;

    int e4 = i & 15;
    int h  = (i >> 4) & 15;
    int s  = (i >> 8) & 2047;
    int n  = i >> 19;

    float4 v = *(const float4*)(src + ((((size_t)n * S_DIM + s) * H_DIM + h) << 6) + e4 * 4);
    uint2 o = make_uint2(pack_f16(v.x, v.y), pack_f16(v.z, v.w));
    *(uint2*)(dst + ((((size_t)n * H_DIM + h) * S_DIM + s) << 6) + e4 * 4) = o;
}

__global__ __launch_bounds__(128, 4) void attn_mma12_kernel(
    const float* __restrict__ Q,
    float* __restrict__ O)
{
    __shared__ __align__(128) char smb[SMEM_BYTES > 17408 ? SMEM_BYTES : 17408];
    float* smf = (float*)smb;
    const uint32_t smu = (uint32_t)__cvta_generic_to_shared(smb);

    const int tid  = threadIdx.x;
    const int w    = tid >> 5;
    const int lane = tid & 31;
    const int g    = lane >> 2;
    const int tg   = lane & 3;
    const int mm   = lane >> 3;
    const int rr   = lane & 7;

    const int qt = blockIdx.x % (L_DIM / BR);
    const int nh = blockIdx.x / (L_DIM / BR);
    const int h  = nh % H_DIM;
    const int n  = nh / H_DIM;
    const int qbase = qt * BR;

    const float* Qg = Q + (((size_t)n * L_DIM + qbase) * H_DIM + h) * 64;

    // ---- Prologue: Q (64x64) -> smem scratch -> fp16 hi/mid A frags ----
    #pragma unroll
    for (int i = 0; i < 8; i++) {
        int idx = i * 128 + tid;
        int row = idx >> 4, c4 = idx & 15;
        float4 v = *(const float4*)(Qg + (size_t)row * (H_DIM * 64) + c4 * 4);
        *(float4*)(smf + row * QSTRIDE + c4 * 4) = v;
    }
    __syncthreads();

    uint32_t qh[16], qm[16];
    {
        const int r0 = w * 16 + g;
        #pragma unroll
        for (int c = 0; c < 4; c++) {
            #pragma unroll
            for (int j = 0; j < 4; j++) {
                int row = r0 + ((j & 1) ? 8 : 0);
                int col = c * 16 + 2 * tg + ((j & 2) ? 8 : 0);
                float2 v = *(const float2*)(smf + row * QSTRIDE + col);
                float x0 = v.x * TEMP, x1 = v.y * TEMP;
                uint32_t hp = pack_f16(x0, x1);
                float2 hf = unpack_f16(hp);
                qh[c * 4 + j] = hp;
                qm[c * 4 + j] = pack_f16(x0 - hf.x, x1 - hf.y);
            }
        }
    }
    __syncthreads();   // scratch reads done before cp.async overwrites region

    float oacc[32];
    #pragma unroll
    for (int i = 0; i < 32; i++) oacc[i] = 0.0f;
    float rs0 = 0.0f, rs1 = 0.0f;

    const uint32_t kadr0 = smu + OFF_KB + (uint32_t)(((mm >> 1) * 8 + rr) * KROWB + (mm & 1) * 16);
    const uint32_t vadr0 = smu + OFF_VB + (uint32_t)(((mm & 1) * 8 + rr) * VROWB + (mm >> 1) * 16);
    // mask: 16x32 fp16 row-major tile per warp; x4 matrices (rowblk, colchunk)
    const uint32_t madr0 = smu + OFF_MB + (uint32_t)((w * 16 + (mm & 1) * 8 + rr) * MROWB + (mm >> 1) * 16);

    // cp.async K/V mapping: rows tid>>3 and +16, 16B chunk (tid&7)
    const int crow = tid >> 3;
    const int ccol = tid & 7;
    const uint16_t* KHb = g_KH + (((size_t)n * H_DIM + h) * S_DIM << 6) + ccol * 8;
    const uint16_t* VHb = g_VH + (((size_t)n * H_DIM + h) * S_DIM << 6) + ccol * 8;
    const uint32_t kdst_t = smu + OFF_KB + crow * KROWB + ccol * 16;
    const uint32_t vdst_t = smu + OFF_VB + crow * VROWB + ccol * 16;

    // cp.async mask mapping: row tid>>1, chunks (tid&1)*2 + {0,1}
    const int mrow = tid >> 1;
    const int mch  = (tid & 1) * 2;
    const uint16_t* MHb = g_MH + (size_t)(qbase + mrow) * S_DIM + mch * 8;
    const uint32_t mdst_t = smu + OFF_MB + mrow * MROWB + mch * 16;

    // issue tile 0
    {
        CP_ASYNC16(kdst_t,               KHb + (size_t)crow * 64);
        CP_ASYNC16(kdst_t + 16 * KROWB,  KHb + (size_t)(crow + 16) * 64);
        CP_ASYNC16(vdst_t,               VHb + (size_t)crow * 64);
        CP_ASYNC16(vdst_t + 16 * VROWB,  VHb + (size_t)(crow + 16) * 64);
        CP_ASYNC16(mdst_t,      MHb);
        CP_ASYNC16(mdst_t + 16, MHb + 8);
        CP_COMMIT();
    }

    for (int t = 0; t < NTILES; ++t) {
        const int buf = t & 1;
        const int s0 = t * BC;

        CP_WAIT0();        // tile t data arrived
        __syncthreads();   // visible; everyone done reading buf^1 (tile t-1)

        // issue tile t+1 into the other buffer (hidden behind compute below)
        if (t + 1 < NTILES) {
            const uint32_t ko = (uint32_t)((1 - buf) * KBUFB);
            const uint32_t vo = (uint32_t)((1 - buf) * VBUFB);
            const uint32_t mo = (uint32_t)((1 - buf) * MBUFB);
            const uint16_t* ks = KHb + (size_t)(s0 + BC) * 64;
            const uint16_t* vs = VHb + (size_t)(s0 + BC) * 64;
            const uint16_t* ms = MHb + (s0 + BC);
            CP_ASYNC16(kdst_t + ko,              ks + (size_t)crow * 64);
            CP_ASYNC16(kdst_t + ko + 16 * KROWB, ks + (size_t)(crow + 16) * 64);
            CP_ASYNC16(vdst_t + vo,              vs + (size_t)crow * 64);
            CP_ASYNC16(vdst_t + vo + 16 * VROWB, vs + (size_t)(crow + 16) * 64);
            CP_ASYNC16(mdst_t + mo,      ms);
            CP_ASYNC16(mdst_t + mo + 16, ms + 8);
            CP_COMMIT();
        }

        // ---- MMA1: sf initialized from mask fragments, then S += (qh+qm)*kh ----
        const uint32_t kadr = kadr0 + buf * KBUFB;
        const uint32_t madr = madr0 + buf * MBUFB;
        float sf[16];
        {
            uint32_t f0, f1, f2, f3, f4, f5, f6, f7;
            LDSM_X4(f0, f1, f2, f3, madr);        // cols 0-15  -> nt 0,1
            LDSM_X4(f4, f5, f6, f7, madr + 32);   // cols 16-31 -> nt 2,3
            float2 a;
            a = unpack_f16(f0); sf[0]  = a.x; sf[1]  = a.y;   // nt0 rows g
            a = unpack_f16(f1); sf[2]  = a.x; sf[3]  = a.y;   // nt0 rows g+8
            a = unpack_f16(f2); sf[4]  = a.x; sf[5]  = a.y;   // nt1 rows g
            a = unpack_f16(f3); sf[6]  = a.x; sf[7]  = a.y;
            a = unpack_f16(f4); sf[8]  = a.x; sf[9]  = a.y;   // nt2
            a = unpack_f16(f5); sf[10] = a.x; sf[11] = a.y;
            a = unpack_f16(f6); sf[12] = a.x; sf[13] = a.y;   // nt3
            a = unpack_f16(f7); sf[14] = a.x; sf[15] = a.y;
        }
        #pragma unroll
        for (int c = 0; c < 4; c++) {
            uint32_t b00, b01, b10, b11, b20, b21, b30, b31;
            LDSM_X4(b00, b01, b10, b11, kadr + c * 32);          // nt 0,1
            LDSM_X4(b20, b21, b30, b31, kadr + c * 32 + 2304);   // nt 2,3
            mma_f16(sf + 0,  qh + c * 4, b00, b01);
            mma_f16(sf + 0,  qm + c * 4, b00, b01);
            mma_f16(sf + 4,  qh + c * 4, b10, b11);
            mma_f16(sf + 4,  qm + c * 4, b10, b11);
            mma_f16(sf + 8,  qh + c * 4, b20, b21);
            mma_f16(sf + 8,  qm + c * 4, b20, b21);
            mma_f16(sf + 12, qh + c * 4, b30, b31);
            mma_f16(sf + 12, qm + c * 4, b30, b31);
        }

        // ---- softmax -> P fp16x2 A-fragments in registers (mask already in sf) ----
        uint32_t u[8];
        #pragma unroll
        for (int nt = 0; nt < 4; nt++) {
            float p0 = __expf(sf[nt * 4 + 0]);
            float p1 = __expf(sf[nt * 4 + 1]);
            float p2 = __expf(sf[nt * 4 + 2]);
            float p3 = __expf(sf[nt * 4 + 3]);
            uint32_t u01 = pack_f16(p0, p1);
            uint32_t u23 = pack_f16(p2, p3);
            float2 t01 = unpack_f16(u01);
            float2 t23 = unpack_f16(u23);
            rs0 += t01.x + t01.y;
            rs1 += t23.x + t23.y;
            u[nt * 2 + 0] = u01;
            u[nt * 2 + 1] = u23;
        }

        // ---- MMA2: O += P * V; A from registers, B via ldmatrix.trans ----
        const uint32_t vadr = vadr0 + buf * VBUFB;
        #pragma unroll
        for (int kc = 0; kc < 2; kc++) {
            const uint32_t* a0 = u + 4 * kc;
            #pragma unroll
            for (int nvp = 0; nvp < 8; nvp += 2) {
                uint32_t v0, v1, v2, v3;
                LDSM_X4_T(v0, v1, v2, v3, vadr + kc * 2304 + nvp * 16);
                mma_f16(oacc + nvp * 4,     a0, v0, v1);
                mma_f16(oacc + nvp * 4 + 4, a0, v2, v3);
            }
        }
    }

    // ---- epilogue ----
    rs0 += __shfl_xor_sync(0xFFFFFFFFu, rs0, 1);
    rs0 += __shfl_xor_sync(0xFFFFFFFFu, rs0, 2);
    rs1 += __shfl_xor_sync(0xFFFFFFFFu, rs1, 1);
    rs1 += __shfl_xor_sync(0xFFFFFFFFu, rs1, 2);
    const float inv0 = 1.0f / rs0;
    const float inv1 = 1.0f / rs1;

    const int qrow0 = qbase + w * 16 + g;
    float* Og0 = O + (((size_t)n * L_DIM + qrow0) * H_DIM + h) * 64;
    float* Og1 = Og0 + (size_t)8 * H_DIM * 64;
    #pragma unroll
    for (int nt = 0; nt < 8; nt++) {
        int c = nt * 8 + tg * 2;
        float2 v0, v1;
        v0.x = oacc[nt * 4 + 0] * inv0;
        v0.y = oacc[nt * 4 + 1] * inv0;
        v1.x = oacc[nt * 4 + 2] * inv1;
        v1.y = oacc[nt * 4 + 3] * inv1;
        *(float2*)(Og0 + c) = v0;
        *(float2*)(Og1 + c) = v1;
    }
}

extern "C" void kernel_launch(void* const* d_in, const int* in_sizes, int n_in,
                              void* d_out, int out_size)
{
    (void)in_sizes; (void)n_in; (void)out_size;
    const float* q = (const float*)d_in[0];
    const float* k = (const float*)d_in[1];
    const float* v = (const float*)d_in[2];
    const float* m = (const float*)d_in[3];
    float* o = (float*)d_out;

    cvt_kernel<<<(2 * GROUPS_PER_T + MGROUPS) / 256, 256>>>(k, v, m);

    dim3 grid(N_DIM * H_DIM * (L_DIM / BR));   // 1024
    dim3 block(128);
    attn_mma12_kernel<<<grid, block>>>(q, o);
}

// round 15
// speedup vs baseline: 1.4713x; 1.1653x over previous
#include <cuda_runtime.h>
#include <cuda_fp16.h>
#include <cstdint>
#include <cstddef>

// Flash attention, all-fp16 operand path, register-resident P, cp.async fp16
// K/V/mask tiles, mask folded into MMA1 C-init via ldmatrix.
//   QK^T: SINGLE fp16 (m16n8k16) -- Q and K both rn-rounded fp16 (err budget
//         measured: ~4.3e-4 predicted vs 1e-3 threshold).
//   PV:   fp16 m16n8k16 f32-accum; P fp16-rounded, rowsum over rounded p.
//   Prepass: K,V f32 -> fp16 (N,H,S,E); mask f32 -> fp16 TEMP*M (L,S).
//   m16-per-warp, 4 CTAs/SM.

#define N_DIM 2
#define L_DIM 2048
#define S_DIM 2048
#define H_DIM 16
#define BR 64
#define BC 32
#define NTILES (S_DIM / BC)
#define TEMP 0.125f

// smem byte layout
#define KROWB 144
#define VROWB 144
#define MROWB 80
#define KBUFB 4608
#define VBUFB 4608
#define MBUFB 5120
#define OFF_KB 0
#define OFF_VB 9216
#define OFF_MB 18432
#define QSTRIDE 68
#define SMEM_BYTES 28672

__device__ __align__(16) uint16_t g_KH[(size_t)N_DIM * H_DIM * S_DIM * 64];
__device__ __align__(16) uint16_t g_VH[(size_t)N_DIM * H_DIM * S_DIM * 64];
__device__ __align__(16) uint16_t g_MH[(size_t)L_DIM * S_DIM];

__device__ __forceinline__ uint32_t pack_f16(float lo, float hi) {
    uint32_t r; asm("cvt.rn.f16x2.f32 %0, %1, %2;" : "=r"(r) : "f"(hi), "f"(lo)); return r;
}
__device__ __forceinline__ float2 unpack_f16(uint32_t u) {
    __half2 h = *reinterpret_cast<__half2*>(&u);
    return __half22float2(h);
}

__device__ __forceinline__ void mma_f16(float* d, const uint32_t* a, uint32_t b0, uint32_t b1) {
    asm volatile(
        "mma.sync.aligned.m16n8k16.row.col.f32.f16.f16.f32 "
        "{%0,%1,%2,%3}, {%4,%5,%6,%7}, {%8,%9}, {%0,%1,%2,%3};"
        : "+f"(d[0]), "+f"(d[1]), "+f"(d[2]), "+f"(d[3])
        : "r"(a[0]), "r"(a[1]), "r"(a[2]), "r"(a[3]), "r"(b0), "r"(b1));
}

#define LDSM_X4(r0, r1, r2, r3, a) \
    asm volatile("ldmatrix.sync.aligned.m8n8.x4.shared.b16 {%0,%1,%2,%3}, [%4];" \
        : "=r"(r0), "=r"(r1), "=r"(r2), "=r"(r3) : "r"(a))
#define LDSM_X4_T(r0, r1, r2, r3, a) \
    asm volatile("ldmatrix.sync.aligned.m8n8.x4.trans.shared.b16 {%0,%1,%2,%3}, [%4];" \
        : "=r"(r0), "=r"(r1), "=r"(r2), "=r"(r3) : "r"(a))

#define CP_ASYNC16(dst, src) \
    asm volatile("cp.async.cg.shared.global [%0], [%1], 16;" :: "r"(dst), "l"(src))
#define CP_COMMIT() asm volatile("cp.async.commit_group;" ::: "memory")
#define CP_WAIT0()  asm volatile("cp.async.wait_group 0;" ::: "memory")

// ---- Prepass ----
#define GROUPS_PER_T ((N_DIM * S_DIM * H_DIM * 64) / 4)
#define MGROUPS ((L_DIM * S_DIM) / 4)

__global__ __launch_bounds__(256) void cvt_kernel(
    const float* __restrict__ K, const float* __restrict__ V,
    const float* __restrict__ M)
{
    int idx = blockIdx.x * blockDim.x + threadIdx.x;
    if (idx >= 2 * GROUPS_PER_T) {                 // mask part
        int i = idx - 2 * GROUPS_PER_T;
        float4 v = *(const float4*)(M + (size_t)i * 4);
        uint2 o = make_uint2(pack_f16(v.x * TEMP, v.y * TEMP),
                             pack_f16(v.z * TEMP, v.w * TEMP));
        *(uint2*)(g_MH + (size_t)i * 4) = o;
        return;
    }
    const bool isV = idx >= GROUPS_PER_T;
    int i = idx & (GROUPS_PER_T - 1);
    const float* src = isV ? V : K;
    uint16_t* dst = isV ? g_VH : g_KH;

    int e4 = i & 15;
    int h  = (i >> 4) & 15;
    int s  = (i >> 8) & 2047;
    int n  = i >> 19;

    float4 v = *(const float4*)(src + ((((size_t)n * S_DIM + s) * H_DIM + h) << 6) + e4 * 4);
    uint2 o = make_uint2(pack_f16(v.x, v.y), pack_f16(v.z, v.w));
    *(uint2*)(dst + ((((size_t)n * H_DIM + h) * S_DIM + s) << 6) + e4 * 4) = o;
}

__global__ __launch_bounds__(128, 4) void attn_mma13_kernel(
    const float* __restrict__ Q,
    float* __restrict__ O)
{
    __shared__ __align__(128) char smb[SMEM_BYTES > 17408 ? SMEM_BYTES : 17408];
    float* smf = (float*)smb;
    const uint32_t smu = (uint32_t)__cvta_generic_to_shared(smb);

    const int tid  = threadIdx.x;
    const int w    = tid >> 5;
    const int lane = tid & 31;
    const int g    = lane >> 2;
    const int tg   = lane & 3;
    const int mm   = lane >> 3;
    const int rr   = lane & 7;

    const int qt = blockIdx.x % (L_DIM / BR);
    const int nh = blockIdx.x / (L_DIM / BR);
    const int h  = nh % H_DIM;
    const int n  = nh / H_DIM;
    const int qbase = qt * BR;

    const float* Qg = Q + (((size_t)n * L_DIM + qbase) * H_DIM + h) * 64;

    // ---- Prologue: Q (64x64) -> smem scratch -> single-fp16 A frags ----
    #pragma unroll
    for (int i = 0; i < 8; i++) {
        int idx = i * 128 + tid;
        int row = idx >> 4, c4 = idx & 15;
        float4 v = *(const float4*)(Qg + (size_t)row * (H_DIM * 64) + c4 * 4);
        *(float4*)(smf + row * QSTRIDE + c4 * 4) = v;
    }
    __syncthreads();

    uint32_t qh[16];
    {
        const int r0 = w * 16 + g;
        #pragma unroll
        for (int c = 0; c < 4; c++) {
            #pragma unroll
            for (int j = 0; j < 4; j++) {
                int row = r0 + ((j & 1) ? 8 : 0);
                int col = c * 16 + 2 * tg + ((j & 2) ? 8 : 0);
                float2 v = *(const float2*)(smf + row * QSTRIDE + col);
                qh[c * 4 + j] = pack_f16(v.x * TEMP, v.y * TEMP);
            }
        }
    }
    __syncthreads();   // scratch reads done before cp.async overwrites region

    float oacc[32];
    #pragma unroll
    for (int i = 0; i < 32; i++) oacc[i] = 0.0f;
    float rs0 = 0.0f, rs1 = 0.0f;

    const uint32_t kadr0 = smu + OFF_KB + (uint32_t)(((mm >> 1) * 8 + rr) * KROWB + (mm & 1) * 16);
    const uint32_t vadr0 = smu + OFF_VB + (uint32_t)(((mm & 1) * 8 + rr) * VROWB + (mm >> 1) * 16);
    const uint32_t madr0 = smu + OFF_MB + (uint32_t)((w * 16 + (mm & 1) * 8 + rr) * MROWB + (mm >> 1) * 16);

    // cp.async K/V mapping
    const int crow = tid >> 3;
    const int ccol = tid & 7;
    const uint16_t* KHb = g_KH + (((size_t)n * H_DIM + h) * S_DIM << 6) + ccol * 8;
    const uint16_t* VHb = g_VH + (((size_t)n * H_DIM + h) * S_DIM << 6) + ccol * 8;
    const uint32_t kdst_t = smu + OFF_KB + crow * KROWB + ccol * 16;
    const uint32_t vdst_t = smu + OFF_VB + crow * VROWB + ccol * 16;

    // cp.async mask mapping
    const int mrow = tid >> 1;
    const int mch  = (tid & 1) * 2;
    const uint16_t* MHb = g_MH + (size_t)(qbase + mrow) * S_DIM + mch * 8;
    const uint32_t mdst_t = smu + OFF_MB + mrow * MROWB + mch * 16;

    // issue tile 0
    {
        CP_ASYNC16(kdst_t,               KHb + (size_t)crow * 64);
        CP_ASYNC16(kdst_t + 16 * KROWB,  KHb + (size_t)(crow + 16) * 64);
        CP_ASYNC16(vdst_t,               VHb + (size_t)crow * 64);
        CP_ASYNC16(vdst_t + 16 * VROWB,  VHb + (size_t)(crow + 16) * 64);
        CP_ASYNC16(mdst_t,      MHb);
        CP_ASYNC16(mdst_t + 16, MHb + 8);
        CP_COMMIT();
    }

    for (int t = 0; t < NTILES; ++t) {
        const int buf = t & 1;
        const int s0 = t * BC;

        CP_WAIT0();
        __syncthreads();

        // issue tile t+1 into the other buffer
        if (t + 1 < NTILES) {
            const uint32_t ko = (uint32_t)((1 - buf) * KBUFB);
            const uint32_t vo = (uint32_t)((1 - buf) * VBUFB);
            const uint32_t mo = (uint32_t)((1 - buf) * MBUFB);
            const uint16_t* ks = KHb + (size_t)(s0 + BC) * 64;
            const uint16_t* vs = VHb + (size_t)(s0 + BC) * 64;
            const uint16_t* ms = MHb + (s0 + BC);
            CP_ASYNC16(kdst_t + ko,              ks + (size_t)crow * 64);
            CP_ASYNC16(kdst_t + ko + 16 * KROWB, ks + (size_t)(crow + 16) * 64);
            CP_ASYNC16(vdst_t + vo,              vs + (size_t)crow * 64);
            CP_ASYNC16(vdst_t + vo + 16 * VROWB, vs + (size_t)(crow + 16) * 64);
            CP_ASYNC16(mdst_t + mo,      ms);
            CP_ASYNC16(mdst_t + mo + 16, ms + 8);
            CP_COMMIT();
        }

        // ---- MMA1: sf = mask (C-init) + qh * kh ----
        const uint32_t kadr = kadr0 + buf * KBUFB;
        const uint32_t madr = madr0 + buf * MBUFB;
        float sf[16];
        {
            uint32_t f0, f1, f2, f3, f4, f5, f6, f7;
            LDSM_X4(f0, f1, f2, f3, madr);
            LDSM_X4(f4, f5, f6, f7, madr + 32);
            float2 a;
            a = unpack_f16(f0); sf[0]  = a.x; sf[1]  = a.y;
            a = unpack_f16(f1); sf[2]  = a.x; sf[3]  = a.y;
            a = unpack_f16(f2); sf[4]  = a.x; sf[5]  = a.y;
            a = unpack_f16(f3); sf[6]  = a.x; sf[7]  = a.y;
            a = unpack_f16(f4); sf[8]  = a.x; sf[9]  = a.y;
            a = unpack_f16(f5); sf[10] = a.x; sf[11] = a.y;
            a = unpack_f16(f6); sf[12] = a.x; sf[13] = a.y;
            a = unpack_f16(f7); sf[14] = a.x; sf[15] = a.y;
        }
        #pragma unroll
        for (int c = 0; c < 4; c++) {
            uint32_t b00, b01, b10, b11, b20, b21, b30, b31;
            LDSM_X4(b00, b01, b10, b11, kadr + c * 32);
            LDSM_X4(b20, b21, b30, b31, kadr + c * 32 + 2304);
            mma_f16(sf + 0,  qh + c * 4, b00, b01);
            mma_f16(sf + 4,  qh + c * 4, b10, b11);
            mma_f16(sf + 8,  qh + c * 4, b20, b21);
            mma_f16(sf + 12, qh + c * 4, b30, b31);
        }

        // ---- softmax -> P fp16x2 A-fragments in registers ----
        uint32_t u[8];
        #pragma unroll
        for (int nt = 0; nt < 4; nt++) {
            float p0 = __expf(sf[nt * 4 + 0]);
            float p1 = __expf(sf[nt * 4 + 1]);
            float p2 = __expf(sf[nt * 4 + 2]);
            float p3 = __expf(sf[nt * 4 + 3]);
            uint32_t u01 = pack_f16(p0, p1);
            uint32_t u23 = pack_f16(p2, p3);
            float2 t01 = unpack_f16(u01);
            float2 t23 = unpack_f16(u23);
            rs0 += t01.x + t01.y;
            rs1 += t23.x + t23.y;
            u[nt * 2 + 0] = u01;
            u[nt * 2 + 1] = u23;
        }

        // ---- MMA2: O += P * V; A from registers, B via ldmatrix.trans ----
        const uint32_t vadr = vadr0 + buf * VBUFB;
        #pragma unroll
        for (int kc = 0; kc < 2; kc++) {
            const uint32_t* a0 = u + 4 * kc;
            #pragma unroll
            for (int nvp = 0; nvp < 8; nvp += 2) {
                uint32_t v0, v1, v2, v3;
                LDSM_X4_T(v0, v1, v2, v3, vadr + kc * 2304 + nvp * 16);
                mma_f16(oacc + nvp * 4,     a0, v0, v1);
                mma_f16(oacc + nvp * 4 + 4, a0, v2, v3);
            }
        }
    }

    // ---- epilogue ----
    rs0 += __shfl_xor_sync(0xFFFFFFFFu, rs0, 1);
    rs0 += __shfl_xor_sync(0xFFFFFFFFu, rs0, 2);
    rs1 += __shfl_xor_sync(0xFFFFFFFFu, rs1, 1);
    rs1 += __shfl_xor_sync(0xFFFFFFFFu, rs1, 2);
    const float inv0 = 1.0f / rs0;
    const float inv1 = 1.0f / rs1;

    const int qrow0 = qbase + w * 16 + g;
    float* Og0 = O + (((size_t)n * L_DIM + qrow0) * H_DIM + h) * 64;
    float* Og1 = Og0 + (size_t)8 * H_DIM * 64;
    #pragma unroll
    for (int nt = 0; nt < 8; nt++) {
        int c = nt * 8 + tg * 2;
        float2 v0, v1;
        v0.x = oacc[nt * 4 + 0] * inv0;
        v0.y = oacc[nt * 4 + 1] * inv0;
        v1.x = oacc[nt * 4 + 2] * inv1;
        v1.y = oacc[nt * 4 + 3] * inv1;
        *(float2*)(Og0 + c) = v0;
        *(float2*)(Og1 + c) = v1;
    }
}

extern "C" void kernel_launch(void* const* d_in, const int* in_sizes, int n_in,
                              void* d_out, int out_size)
{
    (void)in_sizes; (void)n_in; (void)out_size;
    const float* q = (const float*)d_in[0];
    const float* k = (const float*)d_in[1];
    const float* v = (const float*)d_in[2];
    const float* m = (const float*)d_in[3];
    float* o = (float*)d_out;

    cvt_kernel<<<(2 * GROUPS_PER_T + MGROUPS) / 256, 256>>>(k, v, m);

    dim3 grid(N_DIM * H_DIM * (L_DIM / BR));   // 1024
    dim3 block(128);
    attn_mma13_kernel<<<grid, block>>>(q, o);
}

// round 16
// speedup vs baseline: 1.5123x; 1.0279x over previous
#include <cuda_runtime.h>
#include <cuda_fp16.h>
#include <cstdint>
#include <cstddef>

// Flash attention, all-fp16 operand path, register-resident P, cp.async fp16
// K/V/mask tiles, mask folded into MMA1 C-init via ldmatrix.
//   QK^T: single fp16 (m16n8k16), Q pre-scaled by TEMP*log2(e) -> ex2.approx
//   PV:   fp16 m16n8k16 f32-accum; P fp16-rounded.
//   Rowsum: P x ones-B MMA (tensor pipe), no scalar adds, no shfl reduce.
//   m16-per-warp, 4 CTAs/SM.

#define N_DIM 2
#define L_DIM 2048
#define S_DIM 2048
#define H_DIM 16
#define BR 64
#define BC 32
#define NTILES (S_DIM / BC)
#define QSC 0.18033688f        // 0.125 * log2(e)
#define ONESF16X2 0x3C003C00u  // fp16x2 {1.0, 1.0}

// smem byte layout
#define KROWB 144
#define VROWB 144
#define MROWB 80
#define KBUFB 4608
#define VBUFB 4608
#define MBUFB 5120
#define OFF_KB 0
#define OFF_VB 9216
#define OFF_MB 18432
#define QSTRIDE 68
#define SMEM_BYTES 28672

__device__ __align__(16) uint16_t g_KH[(size_t)N_DIM * H_DIM * S_DIM * 64];
__device__ __align__(16) uint16_t g_VH[(size_t)N_DIM * H_DIM * S_DIM * 64];
__device__ __align__(16) uint16_t g_MH[(size_t)L_DIM * S_DIM];   // QSC*M, (L,S)

__device__ __forceinline__ uint32_t pack_f16(float lo, float hi) {
    uint32_t r; asm("cvt.rn.f16x2.f32 %0, %1, %2;" : "=r"(r) : "f"(hi), "f"(lo)); return r;
}
__device__ __forceinline__ float2 unpack_f16(uint32_t u) {
    __half2 h = *reinterpret_cast<__half2*>(&u);
    return __half22float2(h);
}
__device__ __forceinline__ float ex2f(float x) {
    float y; asm("ex2.approx.f32 %0, %1;" : "=f"(y) : "f"(x)); return y;
}

__device__ __forceinline__ void mma_f16(float* d, const uint32_t* a, uint32_t b0, uint32_t b1) {
    asm volatile(
        "mma.sync.aligned.m16n8k16.row.col.f32.f16.f16.f32 "
        "{%0,%1,%2,%3}, {%4,%5,%6,%7}, {%8,%9}, {%0,%1,%2,%3};"
        : "+f"(d[0]), "+f"(d[1]), "+f"(d[2]), "+f"(d[3])
        : "r"(a[0]), "r"(a[1]), "r"(a[2]), "r"(a[3]), "r"(b0), "r"(b1));
}

#define LDSM_X4(r0, r1, r2, r3, a) \
    asm volatile("ldmatrix.sync.aligned.m8n8.x4.shared.b16 {%0,%1,%2,%3}, [%4];" \
        : "=r"(r0), "=r"(r1), "=r"(r2), "=r"(r3) : "r"(a))
#define LDSM_X4_T(r0, r1, r2, r3, a) \
    asm volatile("ldmatrix.sync.aligned.m8n8.x4.trans.shared.b16 {%0,%1,%2,%3}, [%4];" \
        : "=r"(r0), "=r"(r1), "=r"(r2), "=r"(r3) : "r"(a))

#define CP_ASYNC16(dst, src) \
    asm volatile("cp.async.cg.shared.global [%0], [%1], 16;" :: "r"(dst), "l"(src))
#define CP_COMMIT() asm volatile("cp.async.commit_group;" ::: "memory")
#define CP_WAIT0()  asm volatile("cp.async.wait_group 0;" ::: "memory")

// ---- Prepass: K,V f32 -> fp16 (N,H,S,E); mask -> fp16 QSC*M (L,S) ----
#define GROUPS_PER_T ((N_DIM * S_DIM * H_DIM * 64) / 4)
#define MGROUPS ((L_DIM * S_DIM) / 4)

__global__ __launch_bounds__(256) void cvt_kernel(
    const float* __restrict__ K, const float* __restrict__ V,
    const float* __restrict__ M)
{
    int idx = blockIdx.x * blockDim.x + threadIdx.x;
    if (idx >= 2 * GROUPS_PER_T) {                 // mask part
        int i = idx - 2 * GROUPS_PER_T;
        float4 v = *(const float4*)(M + (size_t)i * 4);
        uint2 o = make_uint2(pack_f16(v.x * QSC, v.y * QSC),
                             pack_f16(v.z * QSC, v.w * QSC));
        *(uint2*)(g_MH + (size_t)i * 4) = o;
        return;
    }
    const bool isV = idx >= GROUPS_PER_T;
    int i = idx & (GROUPS_PER_T - 1);
    const float* src = isV ? V : K;
    uint16_t* dst = isV ? g_VH : g_KH;

    int e4 = i & 15;
    int h  = (i >> 4) & 15;
    int s  = (i >> 8) & 2047;
    int n  = i >> 19;

    float4 v = *(const float4*)(src + ((((size_t)n * S_DIM + s) * H_DIM + h) << 6) + e4 * 4);
    uint2 o = make_uint2(pack_f16(v.x, v.y), pack_f16(v.z, v.w));
    *(uint2*)(dst + ((((size_t)n * H_DIM + h) * S_DIM + s) << 6) + e4 * 4) = o;
}

__global__ __launch_bounds__(128, 4) void attn_mma14_kernel(
    const float* __restrict__ Q,
    float* __restrict__ O)
{
    __shared__ __align__(128) char smb[SMEM_BYTES > 17408 ? SMEM_BYTES : 17408];
    float* smf = (float*)smb;
    const uint32_t smu = (uint32_t)__cvta_generic_to_shared(smb);

    const int tid  = threadIdx.x;
    const int w    = tid >> 5;
    const int lane = tid & 31;
    const int g    = lane >> 2;
    const int tg   = lane & 3;
    const int mm   = lane >> 3;
    const int rr   = lane & 7;

    const int qt = blockIdx.x % (L_DIM / BR);
    const int nh = blockIdx.x / (L_DIM / BR);
    const int h  = nh % H_DIM;
    const int n  = nh / H_DIM;
    const int qbase = qt * BR;

    const float* Qg = Q + (((size_t)n * L_DIM + qbase) * H_DIM + h) * 64;

    // ---- Prologue: Q (64x64) -> smem scratch -> fp16 A frags (pre-scaled QSC) ----
    #pragma unroll
    for (int i = 0; i < 8; i++) {
        int idx = i * 128 + tid;
        int row = idx >> 4, c4 = idx & 15;
        float4 v = *(const float4*)(Qg + (size_t)row * (H_DIM * 64) + c4 * 4);
        *(float4*)(smf + row * QSTRIDE + c4 * 4) = v;
    }
    __syncthreads();

    uint32_t qh[16];
    {
        const int r0 = w * 16 + g;
        #pragma unroll
        for (int c = 0; c < 4; c++) {
            #pragma unroll
            for (int j = 0; j < 4; j++) {
                int row = r0 + ((j & 1) ? 8 : 0);
                int col = c * 16 + 2 * tg + ((j & 2) ? 8 : 0);
                float2 v = *(const float2*)(smf + row * QSTRIDE + col);
                qh[c * 4 + j] = pack_f16(v.x * QSC, v.y * QSC);
            }
        }
    }
    __syncthreads();   // scratch reads done before cp.async overwrites region

    float oacc[32];
    #pragma unroll
    for (int i = 0; i < 32; i++) oacc[i] = 0.0f;
    float rsacc[4] = {0.0f, 0.0f, 0.0f, 0.0f};   // rowsum accumulator via ones-MMA

    const uint32_t kadr0 = smu + OFF_KB + (uint32_t)(((mm >> 1) * 8 + rr) * KROWB + (mm & 1) * 16);
    const uint32_t vadr0 = smu + OFF_VB + (uint32_t)(((mm & 1) * 8 + rr) * VROWB + (mm >> 1) * 16);
    const uint32_t madr0 = smu + OFF_MB + (uint32_t)((w * 16 + (mm & 1) * 8 + rr) * MROWB + (mm >> 1) * 16);

    // cp.async K/V mapping
    const int crow = tid >> 3;
    const int ccol = tid & 7;
    const uint16_t* KHb = g_KH + (((size_t)n * H_DIM + h) * S_DIM << 6) + ccol * 8;
    const uint16_t* VHb = g_VH + (((size_t)n * H_DIM + h) * S_DIM << 6) + ccol * 8;
    const uint32_t kdst_t = smu + OFF_KB + crow * KROWB + ccol * 16;
    const uint32_t vdst_t = smu + OFF_VB + crow * VROWB + ccol * 16;

    // cp.async mask mapping
    const int mrow = tid >> 1;
    const int mch  = (tid & 1) * 2;
    const uint16_t* MHb = g_MH + (size_t)(qbase + mrow) * S_DIM + mch * 8;
    const uint32_t mdst_t = smu + OFF_MB + mrow * MROWB + mch * 16;

    // issue tile 0
    {
        CP_ASYNC16(kdst_t,               KHb + (size_t)crow * 64);
        CP_ASYNC16(kdst_t + 16 * KROWB,  KHb + (size_t)(crow + 16) * 64);
        CP_ASYNC16(vdst_t,               VHb + (size_t)crow * 64);
        CP_ASYNC16(vdst_t + 16 * VROWB,  VHb + (size_t)(crow + 16) * 64);
        CP_ASYNC16(mdst_t,      MHb);
        CP_ASYNC16(mdst_t + 16, MHb + 8);
        CP_COMMIT();
    }

    for (int t = 0; t < NTILES; ++t) {
        const int buf = t & 1;
        const int s0 = t * BC;

        CP_WAIT0();
        __syncthreads();

        // issue tile t+1 into the other buffer
        if (t + 1 < NTILES) {
            const uint32_t ko = (uint32_t)((1 - buf) * KBUFB);
            const uint32_t vo = (uint32_t)((1 - buf) * VBUFB);
            const uint32_t mo = (uint32_t)((1 - buf) * MBUFB);
            const uint16_t* ks = KHb + (size_t)(s0 + BC) * 64;
            const uint16_t* vs = VHb + (size_t)(s0 + BC) * 64;
            const uint16_t* ms = MHb + (s0 + BC);
            CP_ASYNC16(kdst_t + ko,              ks + (size_t)crow * 64);
            CP_ASYNC16(kdst_t + ko + 16 * KROWB, ks + (size_t)(crow + 16) * 64);
            CP_ASYNC16(vdst_t + vo,              vs + (size_t)crow * 64);
            CP_ASYNC16(vdst_t + vo + 16 * VROWB, vs + (size_t)(crow + 16) * 64);
            CP_ASYNC16(mdst_t + mo,      ms);
            CP_ASYNC16(mdst_t + mo + 16, ms + 8);
            CP_COMMIT();
        }

        // ---- MMA1: sf = mask (C-init, log2-domain) + qh * kh ----
        const uint32_t kadr = kadr0 + buf * KBUFB;
        const uint32_t madr = madr0 + buf * MBUFB;
        float sf[16];
        {
            uint32_t f0, f1, f2, f3, f4, f5, f6, f7;
            LDSM_X4(f0, f1, f2, f3, madr);
            LDSM_X4(f4, f5, f6, f7, madr + 32);
            float2 a;
            a = unpack_f16(f0); sf[0]  = a.x; sf[1]  = a.y;
            a = unpack_f16(f1); sf[2]  = a.x; sf[3]  = a.y;
            a = unpack_f16(f2); sf[4]  = a.x; sf[5]  = a.y;
            a = unpack_f16(f3); sf[6]  = a.x; sf[7]  = a.y;
            a = unpack_f16(f4); sf[8]  = a.x; sf[9]  = a.y;
            a = unpack_f16(f5); sf[10] = a.x; sf[11] = a.y;
            a = unpack_f16(f6); sf[12] = a.x; sf[13] = a.y;
            a = unpack_f16(f7); sf[14] = a.x; sf[15] = a.y;
        }
        #pragma unroll
        for (int c = 0; c < 4; c++) {
            uint32_t b00, b01, b10, b11, b20, b21, b30, b31;
            LDSM_X4(b00, b01, b10, b11, kadr + c * 32);
            LDSM_X4(b20, b21, b30, b31, kadr + c * 32 + 2304);
            mma_f16(sf + 0,  qh + c * 4, b00, b01);
            mma_f16(sf + 4,  qh + c * 4, b10, b11);
            mma_f16(sf + 8,  qh + c * 4, b20, b21);
            mma_f16(sf + 12, qh + c * 4, b30, b31);
        }

        // ---- softmax: p = 2^sf -> fp16x2 A-fragments (no scalar rowsum) ----
        uint32_t u[8];
        #pragma unroll
        for (int nt = 0; nt < 4; nt++) {
            float p0 = ex2f(sf[nt * 4 + 0]);
            float p1 = ex2f(sf[nt * 4 + 1]);
            float p2 = ex2f(sf[nt * 4 + 2]);
            float p3 = ex2f(sf[nt * 4 + 3]);
            u[nt * 2 + 0] = pack_f16(p0, p1);
            u[nt * 2 + 1] = pack_f16(p2, p3);
        }

        // ---- rowsum via ones-B MMA (tensor pipe; d replicated across n) ----
        mma_f16(rsacc, u,     ONESF16X2, ONESF16X2);
        mma_f16(rsacc, u + 4, ONESF16X2, ONESF16X2);

        // ---- MMA2: O += P * V; A from registers, B via ldmatrix.trans ----
        const uint32_t vadr = vadr0 + buf * VBUFB;
        #pragma unroll
        for (int kc = 0; kc < 2; kc++) {
            const uint32_t* a0 = u + 4 * kc;
            #pragma unroll
            for (int nvp = 0; nvp < 8; nvp += 2) {
                uint32_t v0, v1, v2, v3;
                LDSM_X4_T(v0, v1, v2, v3, vadr + kc * 2304 + nvp * 16);
                mma_f16(oacc + nvp * 4,     a0, v0, v1);
                mma_f16(oacc + nvp * 4 + 4, a0, v2, v3);
            }
        }
    }

    // ---- epilogue (rsacc[0]=rowsum row g, rsacc[2]=row g+8; no reduction) ----
    const float inv0 = 1.0f / rsacc[0];
    const float inv1 = 1.0f / rsacc[2];

    const int qrow0 = qbase + w * 16 + g;
    float* Og0 = O + (((size_t)n * L_DIM + qrow0) * H_DIM + h) * 64;
    float* Og1 = Og0 + (size_t)8 * H_DIM * 64;
    #pragma unroll
    for (int nt = 0; nt < 8; nt++) {
        int c = nt * 8 + tg * 2;
        float2 v0, v1;
        v0.x = oacc[nt * 4 + 0] * inv0;
        v0.y = oacc[nt * 4 + 1] * inv0;
        v1.x = oacc[nt * 4 + 2] * inv1;
        v1.y = oacc[nt * 4 + 3] * inv1;
        *(float2*)(Og0 + c) = v0;
        *(float2*)(Og1 + c) = v1;
    }
}

extern "C" void kernel_launch(void* const* d_in, const int* in_sizes, int n_in,
                              void* d_out, int out_size)
{
    (void)in_sizes; (void)n_in; (void)out_size;
    const float* q = (const float*)d_in[0];
    const float* k = (const float*)d_in[1];
    const float* v = (const float*)d_in[2];
    const float* m = (const float*)d_in[3];
    float* o = (float*)d_out;

    cvt_kernel<<<(2 * GROUPS_PER_T + MGROUPS) / 256, 256>>>(k, v, m);

    dim3 grid(N_DIM * H_DIM * (L_DIM / BR));   // 1024
    dim3 block(128);
    attn_mma14_kernel<<<grid, block>>>(q, o);
}